// round 14
// baseline (speedup 1.0000x reference)
#include <cuda_runtime.h>
#include <cuda_fp16.h>
#include <math.h>
#include <stdint.h>

#define BATCH   8192
#define FPDIM   4860
#define FPPAD   4864
#define EDIM    256
#define HDIM    256
#define VDIM    42
#define TSTEPS  128

// ---------------------------------------------------------------------------
// Static device scratch
// ---------------------------------------------------------------------------
__device__ __half g_x16  [(size_t)BATCH * FPPAD];
__device__ __half g_w1h  [(size_t)2048 * FPPAD];
__device__ __half g_w2h  [(size_t)1024 * 2048];
__device__ __half g_w3h  [(size_t)512 * 1024];
__device__ __half g_w4h  [(size_t)256 * 512];

__device__ __half g_act0h[(size_t)BATCH * 2048];
__device__ __half g_act1h[(size_t)BATCH * 1024];
__device__ __half g_e    [(size_t)BATCH * EDIM];
__device__ __half g_h0buf[2][(size_t)BATCH * HDIM];
__device__ __half g_hist [(size_t)(TSTEPS + 1) * BATCH * HDIM];

// GRU layer weights, virtual-N layout: row = hb*256 + gate*64 + rr, K=512
__device__ __half g_wv[2][(size_t)1024 * 512];
__device__ float  g_bv[2][1024];   // [br | bz | bih_n | bhh_n]

// FC weights padded to 64 rows, fp16; padded bias fp32
__device__ __half g_wfch[64 * 256];
__device__ float  g_bfcp[64];

// ---------------------------------------------------------------------------
// helpers
// ---------------------------------------------------------------------------
__device__ __forceinline__ uint32_t smem_u32(const void* p) {
    return (uint32_t)__cvta_generic_to_shared(p);
}
__device__ __forceinline__ void cp_async16(uint32_t dst, const void* src) {
    asm volatile("cp.async.cg.shared.global [%0], [%1], 16;\n"
                 :: "r"(dst), "l"(src));
}
#define CP_COMMIT()  asm volatile("cp.async.commit_group;\n")
#define CP_WAIT0()   asm volatile("cp.async.wait_group 0;\n")
#define CP_WAIT1()   asm volatile("cp.async.wait_group 1;\n")
#define CP_WAIT2()   asm volatile("cp.async.wait_group 2;\n")

#define SWZ(x) ((x) ^ (((x) >> 3) & 0x70))

__device__ __forceinline__ void ldm4(uint32_t addr, uint32_t& r0, uint32_t& r1,
                                     uint32_t& r2, uint32_t& r3) {
    asm volatile("ldmatrix.sync.aligned.m8n8.x4.shared.b16 {%0,%1,%2,%3}, [%4];"
                 : "=r"(r0), "=r"(r1), "=r"(r2), "=r"(r3) : "r"(addr));
}
__device__ __forceinline__ void mma16816(float c[4], const uint32_t a[4],
                                         uint32_t b0, uint32_t b1) {
    asm volatile("mma.sync.aligned.m16n8k16.row.col.f32.f16.f16.f32 "
                 "{%0,%1,%2,%3}, {%4,%5,%6,%7}, {%8,%9}, {%0,%1,%2,%3};"
                 : "+f"(c[0]), "+f"(c[1]), "+f"(c[2]), "+f"(c[3])
                 : "r"(a[0]), "r"(a[1]), "r"(a[2]), "r"(a[3]),
                   "r"(b0), "r"(b1));
}

__device__ __forceinline__ float sig_(float x)  { return 1.f / (1.f + __expf(-x)); }
__device__ __forceinline__ float tanh_(float x) { float e = __expf(2.f * x); return 1.f - 2.f / (e + 1.f); }

// ---------------------------------------------------------------------------
// Merged GRU step kernel: BOTH layers for one timestep, one launch.
//   CTA = 64 batch rows (grid 128, 1 CTA/SM). States x/h0/h1 (64x256 fp16)
//   preloaded to smem as 4 SW128 chunks of 64x64 cols. 64 kt-stages
//   (2 layers x 4 hb x 8 kt) on a 3-deep 24KB weight ring - never drains.
//   L0 writes h0new to smem (feeds L1 A) + gmem; L1 writes h1new to gmem.
//   8 warps = 2(M) x 4(hq); warp tile M32 x h16, per-thread acc 64 fp32.
// ---------------------------------------------------------------------------
#define S_BSTG   24576                     // 192 rows x 128 B
#define S_RING   (3 * S_BSTG)              // 73728
#define S_SMEM   (S_RING + 4 * 32768 + 1024)   // 205824

__global__ void __launch_bounds__(256, 1)
gru_step(const __half* __restrict__ xin,   // layer0 input (e or h1prev)
         const __half* __restrict__ h0in,  // h0(t-1)
         const __half* __restrict__ h1in,  // h1(t-1)
         const __half* __restrict__ wv0, const float* __restrict__ bv0,
         const __half* __restrict__ wv1, const float* __restrict__ bv1,
         __half* __restrict__ h0out,       // h0(t)
         __half* __restrict__ h1out)       // h1(t) (hist slot t+1)
{
    extern __shared__ char dsm[];
    const uint32_t raw  = smem_u32(dsm);
    const uint32_t ring = (raw + 1023u) & ~1023u;
    const uint32_t xb   = ring + S_RING;       // x      (32KB: 4 chunks)
    const uint32_t h0b  = xb + 32768;          // h0 old
    const uint32_t h1b  = h0b + 32768;         // h1 old
    const uint32_t h0n  = h1b + 32768;         // h0 new

    const int tid  = threadIdx.x;
    const int bm   = blockIdx.x * 64;
    const int w    = tid >> 5;
    const int lane = tid & 31;
    const int mq   = (w & 1) * 32;
    const int hq   = (w >> 1) * 16;

    // ---- preload states (one cp.async group) ----
    auto loadState = [&](uint32_t dst, const __half* src) {
        #pragma unroll
        for (int i = 0; i < 8; i++) {
            const int c = i * 256 + tid;          // 0..2047 16B chunks
            const int row = c >> 5, ch = c & 31;
            const int q = ch >> 3;
            cp_async16(dst + (q << 13) + SWZ((row << 7) + ((ch & 7) << 4)),
                       src + (size_t)(bm + row) * 256 + ch * 8);
        }
    };
    loadState(xb,  xin);
    loadState(h0b, h0in);
    loadState(h1b, h1in);
    CP_COMMIT();

    // ---- weight stage issue: s = layer*32 + hb*8 + kt ----
    auto issueB = [&](int s) {
        const int ly = s >> 5, hb = (s >> 3) & 3, kt = s & 7;
        const __half* wsrc = ly ? wv1 : wv0;
        const uint32_t st = ring + (s % 3) * S_BSTG;
        #pragma unroll
        for (int i = 0; i < 6; i++) {
            const int c = i * 256 + tid;          // 0..1535
            const int rp = c >> 3, cc = c & 7;
            const int g = (rp < 128) ? (rp >> 6) : ((kt < 4) ? 2 : 3);
            const int wrow = g * 64 + (rp & 63);
            cp_async16(st + SWZ((rp << 7) + (cc << 4)),
                       wsrc + ((size_t)(hb << 8) + wrow) * 512 + kt * 64 + cc * 8);
        }
        CP_COMMIT();
    };
    issueB(0); issueB(1); issueB(2);

    const int arow = mq + (lane & 15);
    const int abyt = (lane >> 4) << 4;
    const int brL  = ((lane >> 4) << 3) + (lane & 7);
    const int bbyt = ((lane >> 3) & 1) << 4;

    for (int layer = 0; layer < 2; layer++) {
        const uint32_t Alo = layer ? h0n : xb;
        const uint32_t Ahi = layer ? h1b : h0b;
        const float* bvp   = layer ? bv1 : bv0;

        for (int hb = 0; hb < 4; hb++) {
            float acc[4][2][2][4];
            #pragma unroll
            for (int g = 0; g < 4; g++)
                #pragma unroll
                for (int i = 0; i < 2; i++)
                    #pragma unroll
                    for (int n = 0; n < 2; n++)
                        #pragma unroll
                        for (int q = 0; q < 4; q++) acc[g][i][n][q] = 0.f;

            #pragma unroll
            for (int half = 0; half < 2; half++) {
                const int GX = half ? 3 : 2;
                #pragma unroll
                for (int k4 = 0; k4 < 4; k4++) {
                    const int kt = half * 4 + k4;
                    const int s  = layer * 32 + hb * 8 + kt;
                    CP_WAIT2();
                    __syncthreads();
                    const uint32_t abase = (half ? Ahi : Alo) + (k4 << 13);
                    const uint32_t bst   = ring + (s % 3) * S_BSTG;

                    #pragma unroll
                    for (int ss = 0; ss < 4; ss++) {
                        uint32_t a[2][4];
                        #pragma unroll
                        for (int i = 0; i < 2; i++)
                            ldm4(abase + SWZ(((arow + i * 16) << 7) + ss * 32 + abyt),
                                 a[i][0], a[i][1], a[i][2], a[i][3]);
                        #pragma unroll
                        for (int gi = 0; gi < 3; gi++) {
                            const int ga = (gi < 2) ? gi : GX;
                            uint32_t b0, b1, b2, b3;
                            ldm4(bst + SWZ(((gi * 64 + hq + brL) << 7) + ss * 32 + bbyt),
                                 b0, b1, b2, b3);
                            #pragma unroll
                            for (int i = 0; i < 2; i++) {
                                mma16816(acc[ga][i][0], a[i], b0, b1);
                                mma16816(acc[ga][i][1], a[i], b2, b3);
                            }
                        }
                    }
                    __syncthreads();
                    if (s + 3 < 64) issueB(s + 3);
                    else            CP_COMMIT();
                }
            }

            // ---- epilogue for this (layer, hb): gate math ----
            const uint32_t hsrc = (layer ? h1b : h0b) + (hb << 13);
            const int cq0 = hq + (lane & 3) * 2;
            float2 br[2], bz[2], bi[2], bh[2];
            #pragma unroll
            for (int n2 = 0; n2 < 2; n2++) {
                const int c = hb * 64 + cq0 + n2 * 8;
                br[n2] = *(const float2*)(bvp +       c);
                bz[n2] = *(const float2*)(bvp + 256 + c);
                bi[n2] = *(const float2*)(bvp + 512 + c);
                bh[n2] = *(const float2*)(bvp + 768 + c);
            }
            #pragma unroll
            for (int mf = 0; mf < 2; mf++) {
                #pragma unroll
                for (int n2 = 0; n2 < 2; n2++) {
                    const int cq = cq0 + n2 * 8;
                    #pragma unroll
                    for (int rh = 0; rh < 2; rh++) {
                        const int m = mq + mf * 16 + (lane >> 2) + rh * 8;
                        const float r0 = sig_(acc[0][mf][n2][rh * 2 + 0] + br[n2].x);
                        const float r1 = sig_(acc[0][mf][n2][rh * 2 + 1] + br[n2].y);
                        const float z0 = sig_(acc[1][mf][n2][rh * 2 + 0] + bz[n2].x);
                        const float z1 = sig_(acc[1][mf][n2][rh * 2 + 1] + bz[n2].y);
                        const float n0 = tanh_(acc[2][mf][n2][rh * 2 + 0] + bi[n2].x
                                         + r0 * (acc[3][mf][n2][rh * 2 + 0] + bh[n2].x));
                        const float n1 = tanh_(acc[2][mf][n2][rh * 2 + 1] + bi[n2].y
                                         + r1 * (acc[3][mf][n2][rh * 2 + 1] + bh[n2].y));
                        const uint32_t soff = SWZ((m << 7) + cq * 2);
                        const float2 hp = __half22float2(
                            *(const __half2*)(dsm + (hsrc + soff - raw)));
                        const __half2 hv = __floats2half2_rn(
                            (1.f - z0) * n0 + z0 * hp.x,
                            (1.f - z1) * n1 + z1 * hp.y);
                        if (layer == 0) {
                            *(__half2*)(dsm + (h0n + (hb << 13) + soff - raw)) = hv;
                            *(__half2*)(h0out + (size_t)(bm + m) * 256 + hb * 64 + cq) = hv;
                        } else {
                            *(__half2*)(h1out + (size_t)(bm + m) * 256 + hb * 64 + cq) = hv;
                        }
                    }
                }
            }
        }
    }
}

// ---------------------------------------------------------------------------
// FP16 tensor GEMM for the encoder (unchanged).
// ---------------------------------------------------------------------------
#define NSTG     3
#define TILE_B   16384
#define STAGE_B  (2 * TILE_B)
#define SMEM_TOT (NSTG * STAGE_B)

struct GemmP { const __half* A; const __half* W; const float* bias; __half* C; int ldc; };

template<bool RELU>
__global__ void __launch_bounds__(128, 2)
hgemm(GemmP p0, GemmP p1, int split, int lda, int K)
{
    extern __shared__ __half sh[];
    const uint32_t sbase = smem_u32(sh);

    const int tid  = threadIdx.x;
    int bxx = blockIdx.x;
    GemmP P = p0;
    if (bxx >= split) { P = p1; bxx -= split; }
    const int bm = blockIdx.y * 128;
    const int bn = bxx * 128;

    const int w    = tid >> 5;
    const int lane = tid & 31;
    const int wm   = (w & 1) * 64;
    const int wn   = (w >> 1) * 64;
    const int g    = lane >> 2;
    const int tg   = lane & 3;

    float acc[4][8][4];
    #pragma unroll
    for (int i = 0; i < 4; i++)
        #pragma unroll
        for (int j = 0; j < 8; j++)
            #pragma unroll
            for (int q = 0; q < 4; q++) acc[i][j][q] = 0.f;

    const int KT = K >> 6;
    const __half* A = P.A;
    const __half* W = P.W;

    auto issue = [&](int kt) {
        const uint32_t st = sbase + (kt % NSTG) * STAGE_B;
        const int koff = kt * 64;
        #pragma unroll
        for (int i = 0; i < 8; i++) {
            const int c = i * 128 + tid;
            const int row = c >> 3, col = c & 7;
            cp_async16(st + SWZ((row << 7) + (col << 4)),
                       A + (size_t)(bm + row) * lda + koff + col * 8);
        }
        #pragma unroll
        for (int i = 0; i < 8; i++) {
            const int c = i * 128 + tid;
            const int row = c >> 3, col = c & 7;
            cp_async16(st + TILE_B + SWZ((row << 7) + (col << 4)),
                       W + (size_t)(bn + row) * K + koff + col * 8);
        }
        CP_COMMIT();
    };

    issue(0); issue(1); issue(2);

    const int arow = wm + (lane & 15);
    const int abyt = (lane >> 4) << 4;
    const int brow = wn + ((lane >> 4) << 3) + (lane & 7);
    const int bbyt = ((lane >> 3) & 1) << 4;

    for (int kt = 0; kt < KT; kt++) {
        CP_WAIT2();
        __syncthreads();

        const uint32_t st = sbase + (kt % NSTG) * STAGE_B;

        #pragma unroll
        for (int s = 0; s < 4; s++) {
            uint32_t a[4][4], b[4][4];
            #pragma unroll
            for (int i = 0; i < 4; i++)
                ldm4(st + SWZ(((arow + i * 16) << 7) + s * 32 + abyt),
                     a[i][0], a[i][1], a[i][2], a[i][3]);
            #pragma unroll
            for (int j2 = 0; j2 < 4; j2++)
                ldm4(st + TILE_B + SWZ(((brow + j2 * 16) << 7) + s * 32 + bbyt),
                     b[j2][0], b[j2][1], b[j2][2], b[j2][3]);
            #pragma unroll
            for (int i = 0; i < 4; i++)
                #pragma unroll
                for (int j = 0; j < 8; j++)
                    mma16816(acc[i][j], a[i],
                             b[j >> 1][(j & 1) * 2], b[j >> 1][(j & 1) * 2 + 1]);
        }
        __syncthreads();
        if (kt + NSTG < KT) issue(kt + NSTG);
        else                CP_COMMIT();
    }

    const float* bias = P.bias;
    __half* C = P.C;
    const int ldc = P.ldc;

    float bx[8], by[8];
    #pragma unroll
    for (int j = 0; j < 8; j++) {
        const int n = bn + wn + j * 8 + 2 * tg;
        bx[j] = bias[n]; by[j] = bias[n + 1];
    }
    #pragma unroll
    for (int i = 0; i < 4; i++) {
        const int r0 = bm + wm + i * 16 + g;
        #pragma unroll
        for (int j = 0; j < 8; j++) {
            const int n = bn + wn + j * 8 + 2 * tg;
            float u0 = acc[i][j][0] + bx[j], u1 = acc[i][j][1] + by[j];
            float u2 = acc[i][j][2] + bx[j], u3 = acc[i][j][3] + by[j];
            if (RELU) {
                u0 = fmaxf(u0, 0.f); u1 = fmaxf(u1, 0.f);
                u2 = fmaxf(u2, 0.f); u3 = fmaxf(u3, 0.f);
            }
            *(__half2*)&C[(size_t)r0       * ldc + n] = __floats2half2_rn(u0, u1);
            *(__half2*)&C[(size_t)(r0 + 8) * ldc + n] = __floats2half2_rn(u2, u3);
        }
    }
}

// ---------------------------------------------------------------------------
// Tensor-core FC + fused softmax (unchanged from R12 winner).
// ---------------------------------------------------------------------------
#define F_ATILE  16384
#define F_BTILE  8192
#define F_STAGE  (F_ATILE + F_BTILE)
#define F_PITCH  65
#define F_SEP    (2 * F_STAGE)
#define F_SMEM   (F_SEP + 128 * F_PITCH * 4)

__global__ void __launch_bounds__(128, 2)
fc_softmax_tc(const __half* __restrict__ A,
              const __half* __restrict__ wfch,
              const float*  __restrict__ bfcp,
              float* __restrict__ out)
{
    extern __shared__ __half sh[];
    const uint32_t sbase = smem_u32(sh);
    float* sep = (float*)((char*)sh + F_SEP);

    const int tid  = threadIdx.x;
    const int bm   = blockIdx.x * 128;
    const int w    = tid >> 5;
    const int lane = tid & 31;
    const int wm   = w * 32;
    const int g    = lane >> 2;
    const int tg   = lane & 3;

    float acc[2][8][4];
    #pragma unroll
    for (int i = 0; i < 2; i++)
        #pragma unroll
        for (int j = 0; j < 8; j++)
            #pragma unroll
            for (int q = 0; q < 4; q++) acc[i][j][q] = 0.f;

    auto issue = [&](int kt) {
        const uint32_t st = sbase + (kt & 1) * F_STAGE;
        const int koff = kt * 64;
        #pragma unroll
        for (int i = 0; i < 8; i++) {
            const int c = i * 128 + tid;
            const int row = c >> 3, cc = c & 7;
            cp_async16(st + SWZ((row << 7) + (cc << 4)),
                       A + (size_t)(bm + row) * 256 + koff + cc * 8);
        }
        const uint32_t bB = st + F_ATILE;
        #pragma unroll
        for (int i = 0; i < 4; i++) {
            const int c = i * 128 + tid;
            const int row = c >> 3, cc = c & 7;
            cp_async16(bB + SWZ((row << 7) + (cc << 4)),
                       wfch + (size_t)row * 256 + koff + cc * 8);
        }
        CP_COMMIT();
    };

    issue(0); issue(1);

    const int arow = wm + (lane & 15);
    const int abyt = (lane >> 4) << 4;
    const int brow = ((lane >> 4) << 3) + (lane & 7);
    const int bbyt = ((lane >> 3) & 1) << 4;

    #pragma unroll
    for (int kt = 0; kt < 4; kt++) {
        CP_WAIT1();
        __syncthreads();
        const uint32_t st = sbase + (kt & 1) * F_STAGE;
        const uint32_t bB = st + F_ATILE;

        #pragma unroll
        for (int s = 0; s < 4; s++) {
            uint32_t a[2][4], b[4][4];
            #pragma unroll
            for (int i = 0; i < 2; i++)
                ldm4(st + SWZ(((arow + i * 16) << 7) + s * 32 + abyt),
                     a[i][0], a[i][1], a[i][2], a[i][3]);
            #pragma unroll
            for (int j2 = 0; j2 < 4; j2++)
                ldm4(bB + SWZ(((brow + j2 * 16) << 7) + s * 32 + bbyt),
                     b[j2][0], b[j2][1], b[j2][2], b[j2][3]);
            #pragma unroll
            for (int i = 0; i < 2; i++)
                #pragma unroll
                for (int j = 0; j < 8; j++)
                    mma16816(acc[i][j], a[i],
                             b[j >> 1][(j & 1) * 2], b[j >> 1][(j & 1) * 2 + 1]);
        }
        __syncthreads();
        if (kt + 2 < 4) issue(kt + 2);
        else            CP_COMMIT();
    }
    CP_WAIT0();

    #pragma unroll
    for (int i = 0; i < 2; i++) {
        const int r0 = wm + i * 16 + g;
        #pragma unroll
        for (int j = 0; j < 8; j++) {
            const int n = j * 8 + 2 * tg;
            const float b0 = bfcp[n], b1 = bfcp[n + 1];
            sep[(size_t)r0 * F_PITCH + n]           = fmaxf(acc[i][j][0] + b0, 0.f);
            sep[(size_t)r0 * F_PITCH + n + 1]       = fmaxf(acc[i][j][1] + b1, 0.f);
            sep[(size_t)(r0 + 8) * F_PITCH + n]     = fmaxf(acc[i][j][2] + b0, 0.f);
            sep[(size_t)(r0 + 8) * F_PITCH + n + 1] = fmaxf(acc[i][j][3] + b1, 0.f);
        }
    }
    __syncthreads();

    {
        const int r = wm + lane;
        const float* row = sep + (size_t)r * F_PITCH;
        float v[VDIM];
        float m = -1e30f;
        #pragma unroll
        for (int c = 0; c < VDIM; c++) { v[c] = row[c]; m = fmaxf(m, v[c]); }
        float ssum = 0.f;
        #pragma unroll
        for (int c = 0; c < VDIM; c++) { v[c] = expf(v[c] - m); ssum += v[c]; }
        const float inv = 1.f / ssum;
        const int gr = bm + r;
        const int t  = gr >> 13;
        const int b  = gr & 8191;
        float* o = out + ((size_t)b * TSTEPS + t) * VDIM;
        #pragma unroll
        for (int c = 0; c < VDIM; c++) o[c] = v[c] * inv;
    }
}

// ---------------------------------------------------------------------------
// prep kernels
// ---------------------------------------------------------------------------
__global__ void conv16(const float* __restrict__ src, __half* __restrict__ dst,
                       int N, int K, int Kpad)
{
    const int idx = blockIdx.x * blockDim.x + threadIdx.x;
    if (idx >= N * Kpad) return;
    const int row = idx / Kpad;
    const int k   = idx % Kpad;
    const float v = (k < K) ? src[(size_t)row * K + k] : 0.f;
    dst[idx] = __float2half_rn(v);
}

__global__ void prep_wv(const float* __restrict__ wih, const float* __restrict__ whh,
                        __half* __restrict__ wv)
{
    const int idx = blockIdx.x * blockDim.x + threadIdx.x;
    if (idx >= 1024 * 512) return;
    const int row = idx >> 9;
    const int k   = idx & 511;
    const int hb  = row >> 8;
    const int rem = row & 255;
    const int g   = rem >> 6;
    const int rr  = rem & 63;
    const int hc  = hb * 64 + rr;

    float v = 0.f;
    if (g == 0)      v = (k < 256) ? wih[(size_t)hc * 256 + k]         : whh[(size_t)hc * 256 + k - 256];
    else if (g == 1) v = (k < 256) ? wih[(size_t)(256 + hc) * 256 + k] : whh[(size_t)(256 + hc) * 256 + k - 256];
    else if (g == 2) v = (k < 256) ? wih[(size_t)(512 + hc) * 256 + k] : 0.f;
    else             v = (k < 256) ? 0.f : whh[(size_t)(512 + hc) * 256 + k - 256];
    wv[idx] = __float2half_rn(v);
}

__global__ void prep_bv(const float* __restrict__ bih, const float* __restrict__ bhh,
                        float* __restrict__ bv)
{
    const int idx = blockIdx.x * blockDim.x + threadIdx.x;
    if (idx >= 1024) return;
    const int g = idx >> 8, c = idx & 255;
    float v;
    if (g == 0)      v = bih[c]       + bhh[c];
    else if (g == 1) v = bih[256 + c] + bhh[256 + c];
    else if (g == 2) v = bih[512 + c];
    else             v = bhh[512 + c];
    bv[idx] = v;
}

__global__ void prep_fc(const float* __restrict__ wfc, const float* __restrict__ bfc)
{
    const int idx = blockIdx.x * blockDim.x + threadIdx.x;
    if (idx < 64 * 256) {
        const int row = idx >> 8, k = idx & 255;
        const float v = (row < VDIM) ? wfc[(size_t)row * 256 + k] : 0.f;
        g_wfch[idx] = __float2half_rn(v);
    }
    if (idx < 64) g_bfcp[idx] = (idx < VDIM) ? bfc[idx] : 0.f;
}

__global__ void zero_h(__half* __restrict__ p, int n)
{
    const int idx = blockIdx.x * blockDim.x + threadIdx.x;
    if (idx < n) ((__half2*)p)[idx] = __floats2half2_rn(0.f, 0.f);
}

// ---------------------------------------------------------------------------
// Launch
// ---------------------------------------------------------------------------
extern "C" void kernel_launch(void* const* d_in, const int* in_sizes, int n_in,
                              void* d_out, int out_size)
{
    const float* x    = (const float*)d_in[0];
    const float* w1   = (const float*)d_in[1];
    const float* b1   = (const float*)d_in[2];
    const float* w2   = (const float*)d_in[3];
    const float* b2   = (const float*)d_in[4];
    const float* w3   = (const float*)d_in[5];
    const float* b3   = (const float*)d_in[6];
    const float* w4   = (const float*)d_in[7];
    const float* b4   = (const float*)d_in[8];
    const float* wih0 = (const float*)d_in[9];
    const float* whh0 = (const float*)d_in[10];
    const float* bih0 = (const float*)d_in[11];
    const float* bhh0 = (const float*)d_in[12];
    const float* wih1 = (const float*)d_in[13];
    const float* whh1 = (const float*)d_in[14];
    const float* bih1 = (const float*)d_in[15];
    const float* bhh1 = (const float*)d_in[16];
    const float* wfc  = (const float*)d_in[17];
    const float* bfc  = (const float*)d_in[18];
    float* out = (float*)d_out;

    __half *x16, *w1h, *w2h, *w3h, *w4h, *act0h, *act1h, *e, *hist;
    __half *h0a, *h0b, *wv0, *wv1, *wfch;
    float *bv0, *bv1, *bfcp;
    cudaGetSymbolAddress((void**)&x16,   g_x16);
    cudaGetSymbolAddress((void**)&w1h,   g_w1h);
    cudaGetSymbolAddress((void**)&w2h,   g_w2h);
    cudaGetSymbolAddress((void**)&w3h,   g_w3h);
    cudaGetSymbolAddress((void**)&w4h,   g_w4h);
    cudaGetSymbolAddress((void**)&act0h, g_act0h);
    cudaGetSymbolAddress((void**)&act1h, g_act1h);
    cudaGetSymbolAddress((void**)&e,     g_e);
    cudaGetSymbolAddress((void**)&hist,  g_hist);
    cudaGetSymbolAddress((void**)&wfch,  g_wfch);
    cudaGetSymbolAddress((void**)&bfcp,  g_bfcp);
    { void* p; cudaGetSymbolAddress(&p, g_h0buf); h0a = (__half*)p; h0b = h0a + (size_t)BATCH * HDIM; }
    { void* p; cudaGetSymbolAddress(&p, g_wv);    wv0 = (__half*)p; wv1 = wv0 + (size_t)1024 * 512; }
    { void* p; cudaGetSymbolAddress(&p, g_bv);    bv0 = (float*)p;  bv1 = bv0 + 1024; }

    static bool attr_set = false;
    if (!attr_set) {
        cudaFuncSetAttribute(hgemm<true >,  cudaFuncAttributeMaxDynamicSharedMemorySize, SMEM_TOT);
        cudaFuncSetAttribute(hgemm<false>,  cudaFuncAttributeMaxDynamicSharedMemorySize, SMEM_TOT);
        cudaFuncSetAttribute(gru_step,      cudaFuncAttributeMaxDynamicSharedMemorySize, S_SMEM);
        cudaFuncSetAttribute(fc_softmax_tc, cudaFuncAttributeMaxDynamicSharedMemorySize, F_SMEM);
        attr_set = true;
    }

    const int BH = BATCH * HDIM;

    // ---- prep ----
    #define CONV(src, dst, N, K, Kp) \
        conv16<<<(int)(((size_t)(N) * (Kp) + 255) / 256), 256>>>(src, dst, N, K, Kp)
    CONV(x,  x16, BATCH, FPDIM, FPPAD);
    CONV(w1, w1h, 2048,  FPDIM, FPPAD);
    CONV(w2, w2h, 1024,  2048,  2048);
    CONV(w3, w3h, 512,   1024,  1024);
    CONV(w4, w4h, 256,   512,   512);
    prep_wv<<<(1024 * 512 + 255) / 256, 256>>>(wih0, whh0, wv0);
    prep_wv<<<(1024 * 512 + 255) / 256, 256>>>(wih1, whh1, wv1);
    prep_bv<<<4, 256>>>(bih0, bhh0, bv0);
    prep_bv<<<4, 256>>>(bih1, bhh1, bv1);
    prep_fc<<<64, 256>>>(wfc, bfc);
    zero_h<<<(BH / 2 + 255) / 256, 256>>>(h0a, BH / 2);
    zero_h<<<(BH / 2 + 255) / 256, 256>>>(hist, BH / 2);

    // ---- encoder MLP ----
    {
        GemmP p;
        p = { x16,   w1h, b1, act0h, 2048 };
        hgemm<true><<<dim3(16, 64), 128, SMEM_TOT>>>(p, p, 99, FPPAD, FPPAD);
        p = { act0h, w2h, b2, act1h, 1024 };
        hgemm<true><<<dim3(8,  64), 128, SMEM_TOT>>>(p, p, 99, 2048, 2048);
        p = { act1h, w3h, b3, act0h, 512 };
        hgemm<true><<<dim3(4,  64), 128, SMEM_TOT>>>(p, p, 99, 1024, 1024);
        p = { act0h, w4h, b4, e, 256 };
        hgemm<true><<<dim3(2,  64), 128, SMEM_TOT>>>(p, p, 99, 512, 512);
    }

    // ---- GRU: ONE merged kernel per timestep ----
    for (int t = 0; t < TSTEPS; t++) {
        const __half* xin  = (t == 0) ? e : (hist + (size_t)t * BH);
        const __half* h1in = hist + (size_t)t * BH;          // zeros at t=0
        __half* h0in  = (t & 1) ? h0b : h0a;
        __half* h0out = (t & 1) ? h0a : h0b;
        __half* h1out = hist + (size_t)(t + 1) * BH;

        gru_step<<<BATCH / 64, 256, S_SMEM>>>(xin, h0in, h1in,
                                              wv0, bv0, wv1, bv1,
                                              h0out, h1out);
    }

    // ---- tensor-core FC + fused softmax ----
    fc_softmax_tc<<<(BATCH * TSTEPS) / 128, 128, F_SMEM>>>(hist + BH, wfch, bfcp, out);
}

// round 15
// speedup vs baseline: 1.3375x; 1.3375x over previous
#include <cuda_runtime.h>
#include <cuda_fp16.h>
#include <math.h>
#include <stdint.h>

#define BATCH   8192
#define FPDIM   4860
#define FPPAD   4864
#define EDIM    256
#define HDIM    256
#define VDIM    42
#define TSTEPS  128

// ---------------------------------------------------------------------------
// Static device scratch
// ---------------------------------------------------------------------------
__device__ __half g_x16  [(size_t)BATCH * FPPAD];
__device__ __half g_w1h  [(size_t)2048 * FPPAD];
__device__ __half g_w2h  [(size_t)1024 * 2048];
__device__ __half g_w3h  [(size_t)512 * 1024];
__device__ __half g_w4h  [(size_t)256 * 512];

__device__ __half g_act0h[(size_t)BATCH * 2048];
__device__ __half g_act1h[(size_t)BATCH * 1024];
__device__ __half g_e    [(size_t)BATCH * EDIM];
__device__ __half g_h0buf[2][(size_t)BATCH * HDIM];
__device__ __half g_hist [(size_t)(TSTEPS + 1) * BATCH * HDIM];

// GRU layer weights, virtual-N layout: row = hb*256 + gate*64 + rr, K=512
__device__ __half g_wv[2][(size_t)1024 * 512];
__device__ float  g_bv[2][1024];   // [br | bz | bih_n | bhh_n]

// FC weights padded to 64 rows, fp16; padded bias fp32
__device__ __half g_wfch[64 * 256];
__device__ float  g_bfcp[64];

// ---------------------------------------------------------------------------
// helpers
// ---------------------------------------------------------------------------
__device__ __forceinline__ uint32_t smem_u32(const void* p) {
    return (uint32_t)__cvta_generic_to_shared(p);
}
__device__ __forceinline__ void cp_async16(uint32_t dst, const void* src) {
    asm volatile("cp.async.cg.shared.global [%0], [%1], 16;\n"
                 :: "r"(dst), "l"(src));
}
#define CP_COMMIT()  asm volatile("cp.async.commit_group;\n")
#define CP_WAIT0()   asm volatile("cp.async.wait_group 0;\n")
#define CP_WAIT1()   asm volatile("cp.async.wait_group 1;\n")
#define CP_WAIT2()   asm volatile("cp.async.wait_group 2;\n")

#define SWZ(x) ((x) ^ (((x) >> 3) & 0x70))

__device__ __forceinline__ void ldm4(uint32_t addr, uint32_t& r0, uint32_t& r1,
                                     uint32_t& r2, uint32_t& r3) {
    asm volatile("ldmatrix.sync.aligned.m8n8.x4.shared.b16 {%0,%1,%2,%3}, [%4];"
                 : "=r"(r0), "=r"(r1), "=r"(r2), "=r"(r3) : "r"(addr));
}
__device__ __forceinline__ void mma16816(float c[4], const uint32_t a[4],
                                         uint32_t b0, uint32_t b1) {
    asm volatile("mma.sync.aligned.m16n8k16.row.col.f32.f16.f16.f32 "
                 "{%0,%1,%2,%3}, {%4,%5,%6,%7}, {%8,%9}, {%0,%1,%2,%3};"
                 : "+f"(c[0]), "+f"(c[1]), "+f"(c[2]), "+f"(c[3])
                 : "r"(a[0]), "r"(a[1]), "r"(a[2]), "r"(a[3]),
                   "r"(b0), "r"(b1));
}

__device__ __forceinline__ float sig_(float x)  { return 1.f / (1.f + __expf(-x)); }
__device__ __forceinline__ float tanh_(float x) { float e = __expf(2.f * x); return 1.f - 2.f / (e + 1.f); }

// ---------------------------------------------------------------------------
// Fused GRU layer kernel (R12 winner + 3-stage ring).
//   gates = A_v @ Wv^T where A-lo (kt 0-3) = xin, A-hi (kt 4-7) = hin.
//   CTA: M=64 rows x 64 hidden cols; B tile = 3 active gate strips (192 rows).
//   grid (4, 128), 8 warps: 2 (M) x 4 (h-quarter). 2 CTAs/SM.
// ---------------------------------------------------------------------------
#define L_NSTG    3
#define L_ATILE   8192                     // 64 x 128B
#define L_BTILE   24576                    // 192 x 128B (active strips only)
#define L_STAGE   (L_ATILE + L_BTILE)      // 32 KB
#define L_SMEM    (L_NSTG * L_STAGE)       // 96 KB

__global__ void __launch_bounds__(256, 2)
gru_layer(const __half* __restrict__ xin,   // input sequence element (lda 256)
          const __half* __restrict__ hin,   // hidden state h_{t-1}   (lda 256)
          const __half* __restrict__ wv,    // 1024 x 512 virtual weights
          const float*  __restrict__ bv,    // 1024 biases
          __half* __restrict__ hout)        // new hidden (lda 256)
{
    extern __shared__ __half sh[];
    const uint32_t sbase = smem_u32(sh);

    const int tid  = threadIdx.x;
    const int hb   = blockIdx.x;
    const int bm   = blockIdx.y * 64;
    const int w    = tid >> 5;
    const int lane = tid & 31;
    const int mq   = (w & 1) * 32;
    const int hq   = (w >> 1) * 16;

    float acc[4][2][2][4];
    #pragma unroll
    for (int g = 0; g < 4; g++)
        #pragma unroll
        for (int i = 0; i < 2; i++)
            #pragma unroll
            for (int n = 0; n < 2; n++)
                #pragma unroll
                for (int q = 0; q < 4; q++) acc[g][i][n][q] = 0.f;

    auto issue = [&](int kt) {
        const uint32_t st = sbase + (kt % L_NSTG) * L_STAGE;
        const __half* aptr = (kt < 4) ? xin : hin;
        const int akoff = (kt & 3) * 64;
        #pragma unroll
        for (int i = 0; i < 2; i++) {
            const int c = i * 256 + tid;       // 0..511 chunks (64 rows x 8)
            const int row = c >> 3, cc = c & 7;
            cp_async16(st + SWZ((row << 7) + (cc << 4)),
                       aptr + (size_t)(bm + row) * 256 + akoff + cc * 8);
        }
        const uint32_t bB = st + L_ATILE;
        #pragma unroll
        for (int i = 0; i < 6; i++) {
            const int c = i * 256 + tid;       // 0..1535
            const int rp = c >> 3, cc = c & 7; // rp 0..191
            const int g = (rp < 128) ? (rp >> 6) : ((kt < 4) ? 2 : 3);
            const int wrow = g * 64 + (rp & 63);
            cp_async16(bB + SWZ((rp << 7) + (cc << 4)),
                       wv + ((size_t)(hb << 8) + wrow) * 512 + kt * 64 + cc * 8);
        }
        CP_COMMIT();
    };

    issue(0); issue(1); issue(2);

    const int arow = mq + (lane & 15);
    const int abyt = (lane >> 4) << 4;
    const int brL  = ((lane >> 4) << 3) + (lane & 7);
    const int bbyt = ((lane >> 3) & 1) << 4;

    #pragma unroll
    for (int half = 0; half < 2; half++) {
        const int GX = (half == 0) ? 2 : 3;
        #pragma unroll
        for (int kt4 = 0; kt4 < 4; kt4++) {
            const int kt = half * 4 + kt4;
            CP_WAIT2();
            __syncthreads();
            const uint32_t st = sbase + (kt % L_NSTG) * L_STAGE;
            const uint32_t bB = st + L_ATILE;

            #pragma unroll
            for (int s = 0; s < 4; s++) {
                uint32_t a[2][4];
                #pragma unroll
                for (int i = 0; i < 2; i++)
                    ldm4(st + SWZ(((arow + i * 16) << 7) + s * 32 + abyt),
                         a[i][0], a[i][1], a[i][2], a[i][3]);
                #pragma unroll
                for (int gi = 0; gi < 3; gi++) {
                    const int ga = (gi < 2) ? gi : GX;
                    uint32_t b0, b1, b2, b3;
                    ldm4(bB + SWZ(((gi * 64 + hq + brL) << 7) + s * 32 + bbyt),
                         b0, b1, b2, b3);
                    #pragma unroll
                    for (int i = 0; i < 2; i++) {
                        mma16816(acc[ga][i][0], a[i], b0, b1);
                        mma16816(acc[ga][i][1], a[i], b2, b3);
                    }
                }
            }
            __syncthreads();
            if (kt + L_NSTG < 8) issue(kt + L_NSTG);
            else                 CP_COMMIT();
        }
    }

    // ---- epilogue: per-thread gate math ----
    const int col0 = hb * 64 + hq + (lane & 3) * 2;
    float2 br[2], bz[2], bi[2], bh[2];
    #pragma unroll
    for (int n2 = 0; n2 < 2; n2++) {
        const int c = col0 + n2 * 8;
        br[n2] = *(const float2*)(bv +       c);
        bz[n2] = *(const float2*)(bv + 256 + c);
        bi[n2] = *(const float2*)(bv + 512 + c);
        bh[n2] = *(const float2*)(bv + 768 + c);
    }

    #pragma unroll
    for (int mf = 0; mf < 2; mf++) {
        const int m0 = bm + mq + mf * 16 + (lane >> 2);
        #pragma unroll
        for (int n2 = 0; n2 < 2; n2++) {
            const int col = col0 + n2 * 8;
            #pragma unroll
            for (int rh = 0; rh < 2; rh++) {
                const int m = m0 + rh * 8;
                const float r0 = sig_(acc[0][mf][n2][rh * 2 + 0] + br[n2].x);
                const float r1 = sig_(acc[0][mf][n2][rh * 2 + 1] + br[n2].y);
                const float z0 = sig_(acc[1][mf][n2][rh * 2 + 0] + bz[n2].x);
                const float z1 = sig_(acc[1][mf][n2][rh * 2 + 1] + bz[n2].y);
                const float n0 = tanh_(acc[2][mf][n2][rh * 2 + 0] + bi[n2].x
                                       + r0 * (acc[3][mf][n2][rh * 2 + 0] + bh[n2].x));
                const float n1 = tanh_(acc[2][mf][n2][rh * 2 + 1] + bi[n2].y
                                       + r1 * (acc[3][mf][n2][rh * 2 + 1] + bh[n2].y));
                const __half2 hv = *(const __half2*)(hin + (size_t)m * 256 + col);
                const float2 ho = __half22float2(hv);
                const float h0n = (1.f - z0) * n0 + z0 * ho.x;
                const float h1n = (1.f - z1) * n1 + z1 * ho.y;
                *(__half2*)(hout + (size_t)m * 256 + col) = __floats2half2_rn(h0n, h1n);
            }
        }
    }
}

// ---------------------------------------------------------------------------
// FP16 tensor GEMM for the encoder (unchanged).
// ---------------------------------------------------------------------------
#define NSTG     3
#define TILE_B   16384
#define STAGE_B  (2 * TILE_B)
#define SMEM_TOT (NSTG * STAGE_B)

struct GemmP { const __half* A; const __half* W; const float* bias; __half* C; int ldc; };

template<bool RELU>
__global__ void __launch_bounds__(128, 2)
hgemm(GemmP p0, GemmP p1, int split, int lda, int K)
{
    extern __shared__ __half sh[];
    const uint32_t sbase = smem_u32(sh);

    const int tid  = threadIdx.x;
    int bxx = blockIdx.x;
    GemmP P = p0;
    if (bxx >= split) { P = p1; bxx -= split; }
    const int bm = blockIdx.y * 128;
    const int bn = bxx * 128;

    const int w    = tid >> 5;
    const int lane = tid & 31;
    const int wm   = (w & 1) * 64;
    const int wn   = (w >> 1) * 64;
    const int g    = lane >> 2;
    const int tg   = lane & 3;

    float acc[4][8][4];
    #pragma unroll
    for (int i = 0; i < 4; i++)
        #pragma unroll
        for (int j = 0; j < 8; j++)
            #pragma unroll
            for (int q = 0; q < 4; q++) acc[i][j][q] = 0.f;

    const int KT = K >> 6;
    const __half* A = P.A;
    const __half* W = P.W;

    auto issue = [&](int kt) {
        const uint32_t st = sbase + (kt % NSTG) * STAGE_B;
        const int koff = kt * 64;
        #pragma unroll
        for (int i = 0; i < 8; i++) {
            const int c = i * 128 + tid;
            const int row = c >> 3, col = c & 7;
            cp_async16(st + SWZ((row << 7) + (col << 4)),
                       A + (size_t)(bm + row) * lda + koff + col * 8);
        }
        #pragma unroll
        for (int i = 0; i < 8; i++) {
            const int c = i * 128 + tid;
            const int row = c >> 3, col = c & 7;
            cp_async16(st + TILE_B + SWZ((row << 7) + (col << 4)),
                       W + (size_t)(bn + row) * K + koff + col * 8);
        }
        CP_COMMIT();
    };

    issue(0); issue(1); issue(2);

    const int arow = wm + (lane & 15);
    const int abyt = (lane >> 4) << 4;
    const int brow = wn + ((lane >> 4) << 3) + (lane & 7);
    const int bbyt = ((lane >> 3) & 1) << 4;

    for (int kt = 0; kt < KT; kt++) {
        CP_WAIT2();
        __syncthreads();

        const uint32_t st = sbase + (kt % NSTG) * STAGE_B;

        #pragma unroll
        for (int s = 0; s < 4; s++) {
            uint32_t a[4][4], b[4][4];
            #pragma unroll
            for (int i = 0; i < 4; i++)
                ldm4(st + SWZ(((arow + i * 16) << 7) + s * 32 + abyt),
                     a[i][0], a[i][1], a[i][2], a[i][3]);
            #pragma unroll
            for (int j2 = 0; j2 < 4; j2++)
                ldm4(st + TILE_B + SWZ(((brow + j2 * 16) << 7) + s * 32 + bbyt),
                     b[j2][0], b[j2][1], b[j2][2], b[j2][3]);
            #pragma unroll
            for (int i = 0; i < 4; i++)
                #pragma unroll
                for (int j = 0; j < 8; j++)
                    mma16816(acc[i][j], a[i],
                             b[j >> 1][(j & 1) * 2], b[j >> 1][(j & 1) * 2 + 1]);
        }
        __syncthreads();
        if (kt + NSTG < KT) issue(kt + NSTG);
        else                CP_COMMIT();
    }

    const float* bias = P.bias;
    __half* C = P.C;
    const int ldc = P.ldc;

    float bx[8], by[8];
    #pragma unroll
    for (int j = 0; j < 8; j++) {
        const int n = bn + wn + j * 8 + 2 * tg;
        bx[j] = bias[n]; by[j] = bias[n + 1];
    }
    #pragma unroll
    for (int i = 0; i < 4; i++) {
        const int r0 = bm + wm + i * 16 + g;
        #pragma unroll
        for (int j = 0; j < 8; j++) {
            const int n = bn + wn + j * 8 + 2 * tg;
            float u0 = acc[i][j][0] + bx[j], u1 = acc[i][j][1] + by[j];
            float u2 = acc[i][j][2] + bx[j], u3 = acc[i][j][3] + by[j];
            if (RELU) {
                u0 = fmaxf(u0, 0.f); u1 = fmaxf(u1, 0.f);
                u2 = fmaxf(u2, 0.f); u3 = fmaxf(u3, 0.f);
            }
            *(__half2*)&C[(size_t)r0       * ldc + n] = __floats2half2_rn(u0, u1);
            *(__half2*)&C[(size_t)(r0 + 8) * ldc + n] = __floats2half2_rn(u2, u3);
        }
    }
}

// ---------------------------------------------------------------------------
// Tensor-core FC + fused softmax (unchanged from R12 winner).
// ---------------------------------------------------------------------------
#define F_ATILE  16384
#define F_BTILE  8192
#define F_STAGE  (F_ATILE + F_BTILE)
#define F_PITCH  65
#define F_SEP    (2 * F_STAGE)
#define F_SMEM   (F_SEP + 128 * F_PITCH * 4)

__global__ void __launch_bounds__(128, 2)
fc_softmax_tc(const __half* __restrict__ A,
              const __half* __restrict__ wfch,
              const float*  __restrict__ bfcp,
              float* __restrict__ out)
{
    extern __shared__ __half sh[];
    const uint32_t sbase = smem_u32(sh);
    float* sep = (float*)((char*)sh + F_SEP);

    const int tid  = threadIdx.x;
    const int bm   = blockIdx.x * 128;
    const int w    = tid >> 5;
    const int lane = tid & 31;
    const int wm   = w * 32;
    const int g    = lane >> 2;
    const int tg   = lane & 3;

    float acc[2][8][4];
    #pragma unroll
    for (int i = 0; i < 2; i++)
        #pragma unroll
        for (int j = 0; j < 8; j++)
            #pragma unroll
            for (int q = 0; q < 4; q++) acc[i][j][q] = 0.f;

    auto issue = [&](int kt) {
        const uint32_t st = sbase + (kt & 1) * F_STAGE;
        const int koff = kt * 64;
        #pragma unroll
        for (int i = 0; i < 8; i++) {
            const int c = i * 128 + tid;
            const int row = c >> 3, cc = c & 7;
            cp_async16(st + SWZ((row << 7) + (cc << 4)),
                       A + (size_t)(bm + row) * 256 + koff + cc * 8);
        }
        const uint32_t bB = st + F_ATILE;
        #pragma unroll
        for (int i = 0; i < 4; i++) {
            const int c = i * 128 + tid;
            const int row = c >> 3, cc = c & 7;
            cp_async16(bB + SWZ((row << 7) + (cc << 4)),
                       wfch + (size_t)row * 256 + koff + cc * 8);
        }
        CP_COMMIT();
    };

    issue(0); issue(1);

    const int arow = wm + (lane & 15);
    const int abyt = (lane >> 4) << 4;
    const int brow = ((lane >> 4) << 3) + (lane & 7);
    const int bbyt = ((lane >> 3) & 1) << 4;

    #pragma unroll
    for (int kt = 0; kt < 4; kt++) {
        CP_WAIT1();
        __syncthreads();
        const uint32_t st = sbase + (kt & 1) * F_STAGE;
        const uint32_t bB = st + F_ATILE;

        #pragma unroll
        for (int s = 0; s < 4; s++) {
            uint32_t a[2][4], b[4][4];
            #pragma unroll
            for (int i = 0; i < 2; i++)
                ldm4(st + SWZ(((arow + i * 16) << 7) + s * 32 + abyt),
                     a[i][0], a[i][1], a[i][2], a[i][3]);
            #pragma unroll
            for (int j2 = 0; j2 < 4; j2++)
                ldm4(bB + SWZ(((brow + j2 * 16) << 7) + s * 32 + bbyt),
                     b[j2][0], b[j2][1], b[j2][2], b[j2][3]);
            #pragma unroll
            for (int i = 0; i < 2; i++)
                #pragma unroll
                for (int j = 0; j < 8; j++)
                    mma16816(acc[i][j], a[i],
                             b[j >> 1][(j & 1) * 2], b[j >> 1][(j & 1) * 2 + 1]);
        }
        __syncthreads();
        if (kt + 2 < 4) issue(kt + 2);
        else            CP_COMMIT();
    }
    CP_WAIT0();

    #pragma unroll
    for (int i = 0; i < 2; i++) {
        const int r0 = wm + i * 16 + g;
        #pragma unroll
        for (int j = 0; j < 8; j++) {
            const int n = j * 8 + 2 * tg;
            const float b0 = bfcp[n], b1 = bfcp[n + 1];
            sep[(size_t)r0 * F_PITCH + n]           = fmaxf(acc[i][j][0] + b0, 0.f);
            sep[(size_t)r0 * F_PITCH + n + 1]       = fmaxf(acc[i][j][1] + b1, 0.f);
            sep[(size_t)(r0 + 8) * F_PITCH + n]     = fmaxf(acc[i][j][2] + b0, 0.f);
            sep[(size_t)(r0 + 8) * F_PITCH + n + 1] = fmaxf(acc[i][j][3] + b1, 0.f);
        }
    }
    __syncthreads();

    {
        const int r = wm + lane;
        const float* row = sep + (size_t)r * F_PITCH;
        float v[VDIM];
        float m = -1e30f;
        #pragma unroll
        for (int c = 0; c < VDIM; c++) { v[c] = row[c]; m = fmaxf(m, v[c]); }
        float ssum = 0.f;
        #pragma unroll
        for (int c = 0; c < VDIM; c++) { v[c] = expf(v[c] - m); ssum += v[c]; }
        const float inv = 1.f / ssum;
        const int gr = bm + r;
        const int t  = gr >> 13;
        const int b  = gr & 8191;
        float* o = out + ((size_t)b * TSTEPS + t) * VDIM;
        #pragma unroll
        for (int c = 0; c < VDIM; c++) o[c] = v[c] * inv;
    }
}

// ---------------------------------------------------------------------------
// prep kernels
// ---------------------------------------------------------------------------
__global__ void conv16(const float* __restrict__ src, __half* __restrict__ dst,
                       int N, int K, int Kpad)
{
    const int idx = blockIdx.x * blockDim.x + threadIdx.x;
    if (idx >= N * Kpad) return;
    const int row = idx / Kpad;
    const int k   = idx % Kpad;
    const float v = (k < K) ? src[(size_t)row * K + k] : 0.f;
    dst[idx] = __float2half_rn(v);
}

__global__ void prep_wv(const float* __restrict__ wih, const float* __restrict__ whh,
                        __half* __restrict__ wv)
{
    const int idx = blockIdx.x * blockDim.x + threadIdx.x;
    if (idx >= 1024 * 512) return;
    const int row = idx >> 9;
    const int k   = idx & 511;
    const int hb  = row >> 8;
    const int rem = row & 255;
    const int g   = rem >> 6;
    const int rr  = rem & 63;
    const int hc  = hb * 64 + rr;

    float v = 0.f;
    if (g == 0)      v = (k < 256) ? wih[(size_t)hc * 256 + k]         : whh[(size_t)hc * 256 + k - 256];
    else if (g == 1) v = (k < 256) ? wih[(size_t)(256 + hc) * 256 + k] : whh[(size_t)(256 + hc) * 256 + k - 256];
    else if (g == 2) v = (k < 256) ? wih[(size_t)(512 + hc) * 256 + k] : 0.f;
    else             v = (k < 256) ? 0.f : whh[(size_t)(512 + hc) * 256 + k - 256];
    wv[idx] = __float2half_rn(v);
}

__global__ void prep_bv(const float* __restrict__ bih, const float* __restrict__ bhh,
                        float* __restrict__ bv)
{
    const int idx = blockIdx.x * blockDim.x + threadIdx.x;
    if (idx >= 1024) return;
    const int g = idx >> 8, c = idx & 255;
    float v;
    if (g == 0)      v = bih[c]       + bhh[c];
    else if (g == 1) v = bih[256 + c] + bhh[256 + c];
    else if (g == 2) v = bih[512 + c];
    else             v = bhh[512 + c];
    bv[idx] = v;
}

__global__ void prep_fc(const float* __restrict__ wfc, const float* __restrict__ bfc)
{
    const int idx = blockIdx.x * blockDim.x + threadIdx.x;
    if (idx < 64 * 256) {
        const int row = idx >> 8, k = idx & 255;
        const float v = (row < VDIM) ? wfc[(size_t)row * 256 + k] : 0.f;
        g_wfch[idx] = __float2half_rn(v);
    }
    if (idx < 64) g_bfcp[idx] = (idx < VDIM) ? bfc[idx] : 0.f;
}

__global__ void zero_h(__half* __restrict__ p, int n)
{
    const int idx = blockIdx.x * blockDim.x + threadIdx.x;
    if (idx < n) ((__half2*)p)[idx] = __floats2half2_rn(0.f, 0.f);
}

// ---------------------------------------------------------------------------
// Launch
// ---------------------------------------------------------------------------
extern "C" void kernel_launch(void* const* d_in, const int* in_sizes, int n_in,
                              void* d_out, int out_size)
{
    const float* x    = (const float*)d_in[0];
    const float* w1   = (const float*)d_in[1];
    const float* b1   = (const float*)d_in[2];
    const float* w2   = (const float*)d_in[3];
    const float* b2   = (const float*)d_in[4];
    const float* w3   = (const float*)d_in[5];
    const float* b3   = (const float*)d_in[6];
    const float* w4   = (const float*)d_in[7];
    const float* b4   = (const float*)d_in[8];
    const float* wih0 = (const float*)d_in[9];
    const float* whh0 = (const float*)d_in[10];
    const float* bih0 = (const float*)d_in[11];
    const float* bhh0 = (const float*)d_in[12];
    const float* wih1 = (const float*)d_in[13];
    const float* whh1 = (const float*)d_in[14];
    const float* bih1 = (const float*)d_in[15];
    const float* bhh1 = (const float*)d_in[16];
    const float* wfc  = (const float*)d_in[17];
    const float* bfc  = (const float*)d_in[18];
    float* out = (float*)d_out;

    __half *x16, *w1h, *w2h, *w3h, *w4h, *act0h, *act1h, *e, *hist;
    __half *h0a, *h0b, *wv0, *wv1, *wfch;
    float *bv0, *bv1, *bfcp;
    cudaGetSymbolAddress((void**)&x16,   g_x16);
    cudaGetSymbolAddress((void**)&w1h,   g_w1h);
    cudaGetSymbolAddress((void**)&w2h,   g_w2h);
    cudaGetSymbolAddress((void**)&w3h,   g_w3h);
    cudaGetSymbolAddress((void**)&w4h,   g_w4h);
    cudaGetSymbolAddress((void**)&act0h, g_act0h);
    cudaGetSymbolAddress((void**)&act1h, g_act1h);
    cudaGetSymbolAddress((void**)&e,     g_e);
    cudaGetSymbolAddress((void**)&hist,  g_hist);
    cudaGetSymbolAddress((void**)&wfch,  g_wfch);
    cudaGetSymbolAddress((void**)&bfcp,  g_bfcp);
    { void* p; cudaGetSymbolAddress(&p, g_h0buf); h0a = (__half*)p; h0b = h0a + (size_t)BATCH * HDIM; }
    { void* p; cudaGetSymbolAddress(&p, g_wv);    wv0 = (__half*)p; wv1 = wv0 + (size_t)1024 * 512; }
    { void* p; cudaGetSymbolAddress(&p, g_bv);    bv0 = (float*)p;  bv1 = bv0 + 1024; }

    static bool attr_set = false;
    if (!attr_set) {
        cudaFuncSetAttribute(hgemm<true >,  cudaFuncAttributeMaxDynamicSharedMemorySize, SMEM_TOT);
        cudaFuncSetAttribute(hgemm<false>,  cudaFuncAttributeMaxDynamicSharedMemorySize, SMEM_TOT);
        cudaFuncSetAttribute(gru_layer,     cudaFuncAttributeMaxDynamicSharedMemorySize, L_SMEM);
        cudaFuncSetAttribute(fc_softmax_tc, cudaFuncAttributeMaxDynamicSharedMemorySize, F_SMEM);
        attr_set = true;
    }

    const int BH = BATCH * HDIM;

    // ---- prep ----
    #define CONV(src, dst, N, K, Kp) \
        conv16<<<(int)(((size_t)(N) * (Kp) + 255) / 256), 256>>>(src, dst, N, K, Kp)
    CONV(x,  x16, BATCH, FPDIM, FPPAD);
    CONV(w1, w1h, 2048,  FPDIM, FPPAD);
    CONV(w2, w2h, 1024,  2048,  2048);
    CONV(w3, w3h, 512,   1024,  1024);
    CONV(w4, w4h, 256,   512,   512);
    prep_wv<<<(1024 * 512 + 255) / 256, 256>>>(wih0, whh0, wv0);
    prep_wv<<<(1024 * 512 + 255) / 256, 256>>>(wih1, whh1, wv1);
    prep_bv<<<4, 256>>>(bih0, bhh0, bv0);
    prep_bv<<<4, 256>>>(bih1, bhh1, bv1);
    prep_fc<<<64, 256>>>(wfc, bfc);
    zero_h<<<(BH / 2 + 255) / 256, 256>>>(h0a, BH / 2);
    zero_h<<<(BH / 2 + 255) / 256, 256>>>(hist, BH / 2);

    // ---- encoder MLP ----
    {
        GemmP p;
        p = { x16,   w1h, b1, act0h, 2048 };
        hgemm<true><<<dim3(16, 64), 128, SMEM_TOT>>>(p, p, 99, FPPAD, FPPAD);
        p = { act0h, w2h, b2, act1h, 1024 };
        hgemm<true><<<dim3(8,  64), 128, SMEM_TOT>>>(p, p, 99, 2048, 2048);
        p = { act1h, w3h, b3, act0h, 512 };
        hgemm<true><<<dim3(4,  64), 128, SMEM_TOT>>>(p, p, 99, 1024, 1024);
        p = { act0h, w4h, b4, e, 256 };
        hgemm<true><<<dim3(2,  64), 128, SMEM_TOT>>>(p, p, 99, 512, 512);
    }

    // ---- GRU over T steps: 2 fused layer kernels per step ----
    for (int t = 0; t < TSTEPS; t++) {
        const __half* x0   = (t == 0) ? e : (hist + (size_t)t * BH);
        __half* h0prev = (t & 1) ? h0b : h0a;
        __half* h0new  = (t & 1) ? h0a : h0b;
        const __half* h1prev = hist + (size_t)t * BH;
        __half*       h1new  = hist + (size_t)(t + 1) * BH;

        gru_layer<<<dim3(4, 128), 256, L_SMEM>>>(x0,    h0prev, wv0, bv0, h0new);
        gru_layer<<<dim3(4, 128), 256, L_SMEM>>>(h0new, h1prev, wv1, bv1, h1new);
    }

    // ---- tensor-core FC + fused softmax ----
    fc_softmax_tc<<<(BATCH * TSTEPS) / 128, 128, F_SMEM>>>(hist + BH, wfch, bfcp, out);
}